// round 17
// baseline (speedup 1.0000x reference)
#include <cuda_runtime.h>
#include <cstdint>

#define B_   8
#define N_   784
#define DIM_ 384
#define H_   12
#define HD_  32
#define GS_  28
#define ROWS_ (B_*N_)   // 6272
#define SCALE_ 0.28867513459481287f   // 12^-0.5

__device__ float g_q[B_*H_*N_*HD_];
__device__ float g_k[B_*H_*N_*HD_];
__device__ float g_v[B_*H_*N_*HD_];
__device__ float g_att[B_*N_*DIM_];      // attn output, tf32 bits
__device__ float g_pos[H_*N_*N_];        // normalized positional scores (tf32 bits)
__device__ float g_xt[ROWS_*DIM_];       // x, tf32 bits
__device__ float g_wqkv[3*DIM_*DIM_];    // [Wq|Wk|Wv], tf32 bits
__device__ float g_wo[DIM_*DIM_];        // W_out, tf32 bits

// ---------------------------------------------------------------------------
// helpers
// ---------------------------------------------------------------------------
__device__ __forceinline__ unsigned f2tf(float f) {
    unsigned r; asm("cvt.rna.tf32.f32 %0, %1;" : "=r"(r) : "f"(f)); return r;
}
__device__ __forceinline__ void mma8(float4& d,
                                     unsigned a0, unsigned a1, unsigned a2, unsigned a3,
                                     unsigned b0, unsigned b1) {
    asm volatile("mma.sync.aligned.m16n8k8.row.col.f32.tf32.tf32.f32 "
                 "{%0,%1,%2,%3}, {%4,%5,%6,%7}, {%8,%9}, {%0,%1,%2,%3};\n"
                 : "+f"(d.x), "+f"(d.y), "+f"(d.z), "+f"(d.w)
                 : "r"(a0), "r"(a1), "r"(a2), "r"(a3), "r"(b0), "r"(b1));
}
__device__ __forceinline__ void cpa16(void* s, const void* g, bool pred) {
    unsigned sa = (unsigned)__cvta_generic_to_shared(s);
    int sz = pred ? 16 : 0;
    asm volatile("cp.async.cg.shared.global [%0], [%1], 16, %2;\n"
                 :: "r"(sa), "l"(g), "r"(sz) : "memory");
}
__device__ __forceinline__ void cpa_commit() {
    asm volatile("cp.async.commit_group;\n" ::: "memory");
}
__device__ __forceinline__ uint4 ldm4(unsigned addr) {
    uint4 v;
    asm volatile("ldmatrix.sync.aligned.m8n8.x4.shared.b16 {%0,%1,%2,%3}, [%4];\n"
                 : "=r"(v.x), "=r"(v.y), "=r"(v.z), "=r"(v.w) : "r"(addr));
    return v;
}

// ---------------------------------------------------------------------------
// Kernel 0: one-shot fp32 -> tf32-bit conversion of x and weights
// ---------------------------------------------------------------------------
__global__ void cvt_kernel(const float* __restrict__ x,
                           const float* __restrict__ Wq,
                           const float* __restrict__ Wk,
                           const float* __restrict__ Wv,
                           const float* __restrict__ Wo) {
    int stride = gridDim.x * blockDim.x;
    const int WSZ4 = DIM_ * DIM_ / 4;
    for (int i = blockIdx.x * blockDim.x + threadIdx.x; i < ROWS_ * DIM_ / 4; i += stride) {
        float4 v = ((const float4*)x)[i];
        ((uint4*)g_xt)[i] = make_uint4(f2tf(v.x), f2tf(v.y), f2tf(v.z), f2tf(v.w));
    }
    for (int i = blockIdx.x * blockDim.x + threadIdx.x; i < WSZ4; i += stride) {
        float4 a = ((const float4*)Wq)[i];
        ((uint4*)g_wqkv)[i] = make_uint4(f2tf(a.x), f2tf(a.y), f2tf(a.z), f2tf(a.w));
        float4 b = ((const float4*)Wk)[i];
        ((uint4*)g_wqkv)[WSZ4 + i] = make_uint4(f2tf(b.x), f2tf(b.y), f2tf(b.z), f2tf(b.w));
        float4 c = ((const float4*)Wv)[i];
        ((uint4*)g_wqkv)[2 * WSZ4 + i] = make_uint4(f2tf(c.x), f2tf(c.y), f2tf(c.z), f2tf(c.w));
        float4 d = ((const float4*)Wo)[i];
        ((uint4*)g_wo)[i] = make_uint4(f2tf(d.x), f2tf(d.y), f2tf(d.z), f2tf(d.w));
    }
}

// ---------------------------------------------------------------------------
// Kernel 1: normalized positional softmax  pos[h][n][m]  (writes tf32 bits)
// ---------------------------------------------------------------------------
__global__ void pos_kernel(const float* __restrict__ W_pos,
                           const float* __restrict__ b_pos) {
    int hn = blockIdx.x;
    int h = hn / N_, n = hn - h * N_;
    int nx = n % GS_, ny = n / GS_;
    float w0 = W_pos[h*3+0], w1 = W_pos[h*3+1], w2 = W_pos[h*3+2], bp = b_pos[h];
    int t = threadIdx.x;

    float lg[4];
    float lmax = -1e30f;
#pragma unroll
    for (int i = 0; i < 4; i++) {
        int m = t + i * 256;
        if (m < N_) {
            int mx = m % GS_, my = m / GS_;
            float dx = (float)(mx - nx), dy = (float)(my - ny);
            float v = fmaf(w2, dx*dx + dy*dy, fmaf(w1, dy, fmaf(w0, dx, bp)));
            lg[i] = v;
            lmax = fmaxf(lmax, v);
        } else lg[i] = -1e30f;
    }
    __shared__ float sred[8];
    __shared__ float ssum[8];
#pragma unroll
    for (int o = 16; o > 0; o >>= 1)
        lmax = fmaxf(lmax, __shfl_xor_sync(0xffffffffu, lmax, o));
    if ((t & 31) == 0) sred[t >> 5] = lmax;
    __syncthreads();
    float bmax = fmaxf(fmaxf(fmaxf(sred[0], sred[1]), fmaxf(sred[2], sred[3])),
                       fmaxf(fmaxf(sred[4], sred[5]), fmaxf(sred[6], sred[7])));

    float e[4]; float lsum = 0.f;
#pragma unroll
    for (int i = 0; i < 4; i++) { e[i] = __expf(lg[i] - bmax); lsum += e[i]; }
#pragma unroll
    for (int o = 16; o > 0; o >>= 1)
        lsum += __shfl_xor_sync(0xffffffffu, lsum, o);
    if ((t & 31) == 0) ssum[t >> 5] = lsum;
    __syncthreads();
    float tot = ((ssum[0]+ssum[1])+(ssum[2]+ssum[3]))+((ssum[4]+ssum[5])+(ssum[6]+ssum[7]));
    float inv = 1.f / tot;

    float* outp = g_pos + (size_t)hn * N_;
#pragma unroll
    for (int i = 0; i < 4; i++) {
        int m = t + i * 256;
        if (m < N_) outp[m] = __uint_as_float(f2tf(e[i] * inv));
    }
}

// ---------------------------------------------------------------------------
// Kernel 2: fused QKV tf32 GEMM (ldmatrix frags + pre-converted inputs:
// fill is raw uint4 LDG->STS, zero cvt in the loop)
// ---------------------------------------------------------------------------
#define GSTR 36
__global__ __launch_bounds__(128) void gemm_qkv() {
    __shared__ unsigned Xs[2][64][GSTR];
    __shared__ unsigned Ws[2][64][GSTR];

    int t = threadIdx.x, w = t >> 5, lane = t & 31;
    int ly = lane >> 2, lx = lane & 3;
    int wr = w >> 1, wc = w & 1;
    int row0 = blockIdx.y * 64, col0 = blockIdx.x * 64;
    int wsel = col0 / DIM_;
    int colw = col0 - wsel * DIM_;
    const unsigned* X = (const unsigned*)g_xt;
    const unsigned* W = (const unsigned*)g_wqkv + (size_t)wsel * DIM_ * DIM_;
    float* Op = (wsel == 0) ? g_q : (wsel == 1) ? g_k : g_v;
    float scale = (wsel == 0) ? SCALE_ : 1.f;

    int g8 = lane >> 3, l7 = lane & 7;
    unsigned arow = (unsigned)(wr * 32 + (g8 & 1) * 8 + l7);
    unsigned acol = (unsigned)((g8 >> 1) * 4);
    unsigned brow = (unsigned)(wc * 32 + (g8 >> 1) * 8 + l7);
    unsigned bcol = (unsigned)((g8 & 1) * 4);
    unsigned xsb = (unsigned)__cvta_generic_to_shared(&Xs[0][0][0]);
    unsigned wsb = (unsigned)__cvta_generic_to_shared(&Ws[0][0][0]);
    const unsigned BUF = 64u * GSTR * 4u;

    uint4 rx[4], rw[4];
#pragma unroll
    for (int l = 0; l < 4; l++) {
        int idx = t + l * 128;
        int r = idx >> 3, kq = (idx & 7) << 2;
        rx[l] = *(const uint4*)&X[(size_t)(row0 + r) * DIM_ + kq];
        rw[l] = *(const uint4*)&W[(size_t)(colw + r) * DIM_ + kq];
    }
#pragma unroll
    for (int l = 0; l < 4; l++) {
        int idx = t + l * 128;
        int r = idx >> 3, kq = (idx & 7) << 2;
        *(uint4*)&Xs[0][r][kq] = rx[l];
        *(uint4*)&Ws[0][r][kq] = rw[l];
    }
    __syncthreads();

    float4 acc[2][4];
#pragma unroll
    for (int i = 0; i < 2; i++)
#pragma unroll
        for (int j = 0; j < 4; j++) acc[i][j] = make_float4(0.f, 0.f, 0.f, 0.f);

    for (int ki = 0; ki < 12; ki++) {
        int cur = ki & 1;
        unsigned xsc = xsb + cur * BUF;
        unsigned wsc = wsb + cur * BUF;
        if (ki < 11) {
            int k0 = (ki + 1) * 32;
#pragma unroll
            for (int l = 0; l < 4; l++) {
                int idx = t + l * 128;
                int r = idx >> 3, kq = (idx & 7) << 2;
                rx[l] = *(const uint4*)&X[(size_t)(row0 + r) * DIM_ + k0 + kq];
                rw[l] = *(const uint4*)&W[(size_t)(colw + r) * DIM_ + k0 + kq];
            }
        }
#pragma unroll
        for (int kk = 0; kk < 4; kk++) {
            int K0 = kk * 8;
            uint4 A0 = ldm4(xsc + (((arow) * GSTR + acol + K0) << 2));
            uint4 A1 = ldm4(xsc + (((arow + 16) * GSTR + acol + K0) << 2));
#pragma unroll
            for (int ntp = 0; ntp < 2; ntp++) {
                uint4 BB = ldm4(wsc + (((brow + ntp * 16) * GSTR + bcol + K0) << 2));
                mma8(acc[0][ntp*2],   A0.x, A0.y, A0.z, A0.w, BB.x, BB.y);
                mma8(acc[1][ntp*2],   A1.x, A1.y, A1.z, A1.w, BB.x, BB.y);
                mma8(acc[0][ntp*2+1], A0.x, A0.y, A0.z, A0.w, BB.z, BB.w);
                mma8(acc[1][ntp*2+1], A1.x, A1.y, A1.z, A1.w, BB.z, BB.w);
            }
        }
        if (ki < 11) {
            int nxt = (ki + 1) & 1;
#pragma unroll
            for (int l = 0; l < 4; l++) {
                int idx = t + l * 128;
                int r = idx >> 3, kq = (idx & 7) << 2;
                *(uint4*)&Xs[nxt][r][kq] = rx[l];
                *(uint4*)&Ws[nxt][r][kq] = rw[l];
            }
        }
        __syncthreads();
    }

    int h = (colw + wc * 32) >> 5;
#pragma unroll
    for (int mi = 0; mi < 2; mi++) {
        int row = row0 + wr * 32 + mi * 16 + ly;
#pragma unroll
        for (int nt = 0; nt < 4; nt++) {
            int d = nt * 8 + lx * 2;
            {
                int b = row / N_, n = row - b * N_;
                float2 v;
                v.x = __uint_as_float(f2tf(acc[mi][nt].x * scale));
                v.y = __uint_as_float(f2tf(acc[mi][nt].y * scale));
                *(float2*)&Op[(((size_t)(b * H_ + h)) * N_ + n) * HD_ + d] = v;
            }
            {
                int row2 = row + 8;
                int b = row2 / N_, n = row2 - b * N_;
                float2 v;
                v.x = __uint_as_float(f2tf(acc[mi][nt].z * scale));
                v.y = __uint_as_float(f2tf(acc[mi][nt].w * scale));
                *(float2*)&Op[(((size_t)(b * H_ + h)) * N_ + n) * HD_ + d] = v;
            }
        }
    }
}

// ---------------------------------------------------------------------------
// Kernel 2b: out-projection tf32 GEMM (ldmatrix + pre-converted inputs)
// ---------------------------------------------------------------------------
__global__ __launch_bounds__(128) void gemm_out(
    const float* __restrict__ bias, float* __restrict__ OUTp)
{
    __shared__ unsigned Xs[2][64][GSTR];
    __shared__ unsigned Ws[2][64][GSTR];

    int t = threadIdx.x, w = t >> 5, lane = t & 31;
    int ly = lane >> 2, lx = lane & 3;
    int wr = w >> 1, wc = w & 1;
    int row0 = blockIdx.y * 64, col0 = blockIdx.x * 64;
    const unsigned* X = (const unsigned*)g_att;
    const unsigned* W = (const unsigned*)g_wo;

    int g8 = lane >> 3, l7 = lane & 7;
    unsigned arow = (unsigned)(wr * 32 + (g8 & 1) * 8 + l7);
    unsigned acol = (unsigned)((g8 >> 1) * 4);
    unsigned brow = (unsigned)(wc * 32 + (g8 >> 1) * 8 + l7);
    unsigned bcol = (unsigned)((g8 & 1) * 4);
    unsigned xsb = (unsigned)__cvta_generic_to_shared(&Xs[0][0][0]);
    unsigned wsb = (unsigned)__cvta_generic_to_shared(&Ws[0][0][0]);
    const unsigned BUF = 64u * GSTR * 4u;

    uint4 rx[4], rw[4];
#pragma unroll
    for (int l = 0; l < 4; l++) {
        int idx = t + l * 128;
        int r = idx >> 3, kq = (idx & 7) << 2;
        rx[l] = *(const uint4*)&X[(size_t)(row0 + r) * DIM_ + kq];
        rw[l] = *(const uint4*)&W[(size_t)(col0 + r) * DIM_ + kq];
    }
#pragma unroll
    for (int l = 0; l < 4; l++) {
        int idx = t + l * 128;
        int r = idx >> 3, kq = (idx & 7) << 2;
        *(uint4*)&Xs[0][r][kq] = rx[l];
        *(uint4*)&Ws[0][r][kq] = rw[l];
    }
    __syncthreads();

    float4 acc[2][4];
#pragma unroll
    for (int i = 0; i < 2; i++)
#pragma unroll
        for (int j = 0; j < 4; j++) acc[i][j] = make_float4(0.f, 0.f, 0.f, 0.f);

    for (int ki = 0; ki < 12; ki++) {
        int cur = ki & 1;
        unsigned xsc = xsb + cur * BUF;
        unsigned wsc = wsb + cur * BUF;
        if (ki < 11) {
            int k0 = (ki + 1) * 32;
#pragma unroll
            for (int l = 0; l < 4; l++) {
                int idx = t + l * 128;
                int r = idx >> 3, kq = (idx & 7) << 2;
                rx[l] = *(const uint4*)&X[(size_t)(row0 + r) * DIM_ + k0 + kq];
                rw[l] = *(const uint4*)&W[(size_t)(col0 + r) * DIM_ + k0 + kq];
            }
        }
#pragma unroll
        for (int kk = 0; kk < 4; kk++) {
            int K0 = kk * 8;
            uint4 A0 = ldm4(xsc + (((arow) * GSTR + acol + K0) << 2));
            uint4 A1 = ldm4(xsc + (((arow + 16) * GSTR + acol + K0) << 2));
#pragma unroll
            for (int ntp = 0; ntp < 2; ntp++) {
                uint4 BB = ldm4(wsc + (((brow + ntp * 16) * GSTR + bcol + K0) << 2));
                mma8(acc[0][ntp*2],   A0.x, A0.y, A0.z, A0.w, BB.x, BB.y);
                mma8(acc[1][ntp*2],   A1.x, A1.y, A1.z, A1.w, BB.x, BB.y);
                mma8(acc[0][ntp*2+1], A0.x, A0.y, A0.z, A0.w, BB.z, BB.w);
                mma8(acc[1][ntp*2+1], A1.x, A1.y, A1.z, A1.w, BB.z, BB.w);
            }
        }
        if (ki < 11) {
            int nxt = (ki + 1) & 1;
#pragma unroll
            for (int l = 0; l < 4; l++) {
                int idx = t + l * 128;
                int r = idx >> 3, kq = (idx & 7) << 2;
                *(uint4*)&Xs[nxt][r][kq] = rx[l];
                *(uint4*)&Ws[nxt][r][kq] = rw[l];
            }
        }
        __syncthreads();
    }

#pragma unroll
    for (int mi = 0; mi < 2; mi++) {
        int row = row0 + wr * 32 + mi * 16 + ly;
#pragma unroll
        for (int nt = 0; nt < 4; nt++) {
            int col = col0 + wc * 32 + nt * 8 + lx * 2;
            float b0 = bias[col], b1 = bias[col + 1];
            float2 v0; v0.x = acc[mi][nt].x + b0; v0.y = acc[mi][nt].y + b1;
            *(float2*)&OUTp[(size_t)row * DIM_ + col] = v0;
            float2 v1; v1.x = acc[mi][nt].z + b0; v1.y = acc[mi][nt].w + b1;
            *(float2*)&OUTp[(size_t)(row + 8) * DIM_ + col] = v1;
        }
    }
}

// ---------------------------------------------------------------------------
// Kernel 3: fused gated attention (round-16 champion; epilogue now writes
// tf32 bits into g_att for gemm_out's raw fill)
// ---------------------------------------------------------------------------
#define QSTR 36
#define VSTR 40
#define PSTR 68
struct ASmem {
    unsigned P1[64][PSTR];
    unsigned P2[64][PSTR];
    unsigned Ks[2][64][QSTR];
    unsigned Vs[2][64][VSTR];
};   // 73728 B -> 3 blocks/SM

__global__ __launch_bounds__(128) void attn_kernel(const float* __restrict__ gating) {
    extern __shared__ char sraw[];
    ASmem& S = *reinterpret_cast<ASmem*>(sraw);

    int t = threadIdx.x, w = t >> 5, lane = t & 31;
    int ly = lane >> 2, lx = lane & 3;
    int bh = blockIdx.y;
    int b = bh / H_, h = bh - b * H_;
    int q0 = blockIdx.x * 64;
    int R0 = w * 16;

    int g8 = lane >> 3, l7 = lane & 7;
    unsigned aoff = (unsigned)((R0 + (g8 & 1) * 8 + l7) * PSTR + (g8 >> 1) * 4) << 2;
    unsigned brow = (unsigned)((g8 >> 1) * 8 + l7);
    unsigned bcol = (unsigned)((g8 & 1) * 4);
    unsigned p1base = (unsigned)__cvta_generic_to_shared(&S.P1[0][0]) + aoff;
    unsigned p2base = (unsigned)__cvta_generic_to_shared(&S.P2[0][0]) + aoff;
    unsigned ksb0   = (unsigned)__cvta_generic_to_shared(&S.Ks[0][0][0]);

    const float* Qg   = g_q + (size_t)bh * N_ * HD_;
    const float* Kg   = g_k + (size_t)bh * N_ * HD_;
    const float* Vg   = g_v + (size_t)bh * N_ * HD_;
    const float* POSg = g_pos + (size_t)h * N_ * N_;

    float gate = 1.f / (1.f + __expf(-gating[h]));

#pragma unroll
    for (int l = 0; l < 4; l++) {
        int idx = t + l * 128;
        int r = idx >> 3, dq = (idx & 7) << 2;
        cpa16(&S.P2[r][dq], &Qg[(size_t)(q0 + r) * HD_ + dq], q0 + r < N_);
        bool mv = r < N_;
        cpa16(&S.Ks[0][r][dq], &Kg[(size_t)r * HD_ + dq], mv);
        cpa16(&S.Vs[0][r][dq], &Vg[(size_t)r * HD_ + dq], mv);
    }
    cpa_commit();
    asm volatile("cp.async.wait_group 0;\n" ::: "memory");
    __syncthreads();

    unsigned qf[4][4];
#pragma unroll
    for (int kk = 0; kk < 4; kk++) {
        int K0 = kk * 8;
        qf[kk][0] = S.P2[R0 + ly][K0 + lx];
        qf[kk][1] = S.P2[R0 + ly + 8][K0 + lx];
        qf[kk][2] = S.P2[R0 + ly][K0 + lx + 4];
        qf[kk][3] = S.P2[R0 + ly + 8][K0 + lx + 4];
    }
    __syncwarp();

#pragma unroll
    for (int l = 0; l < 8; l++) {
        int idx = lane + l * 32;
        int rr = idx >> 4, cq = (idx & 15) << 2;
        cpa16(&S.P2[R0 + rr][cq], &POSg[(size_t)(q0 + R0 + rr) * N_ + cq],
              (q0 + R0 + rr < N_) && (cq < N_));
    }
    cpa_commit();   // per-thread FIFO: { P2[0] }

    float4 opat[4], opos[4];
#pragma unroll
    for (int i = 0; i < 4; i++) { opat[i] = make_float4(0.f,0.f,0.f,0.f); opos[i] = opat[i]; }
    float rs0 = 0.f, rs1 = 0.f;

    for (int it = 0; it < 12; it++) {
        int cur = it & 1;
        int nxt = (it + 1) & 1;
        int m1 = (it + 1) * 64;
        unsigned ksc = ksb0 + (unsigned)(cur * 64 * QSTR) * 4u;
#pragma unroll
        for (int l = 0; l < 4; l++) {
            int idx = t + l * 128;
            int r = idx >> 3, dq = (idx & 7) << 2;
            bool mv = m1 + r < N_;
            cpa16(&S.Ks[nxt][r][dq], &Kg[(size_t)(m1 + r) * HD_ + dq], mv);
            cpa16(&S.Vs[nxt][r][dq], &Vg[(size_t)(m1 + r) * HD_ + dq], mv);
        }
        cpa_commit();

        float4 sacc[8];
#pragma unroll
        for (int i = 0; i < 8; i++) sacc[i] = make_float4(0.f,0.f,0.f,0.f);
#pragma unroll
        for (int kk = 0; kk < 4; kk++) {
            int K0 = kk * 8;
#pragma unroll
            for (int ntp = 0; ntp < 4; ntp++) {
                unsigned addr = ksc + (((ntp * 16 + brow) * QSTR + bcol + K0) << 2);
                uint4 bb = ldm4(addr);
                mma8(sacc[ntp*2],   qf[kk][0], qf[kk][1], qf[kk][2], qf[kk][3], bb.x, bb.y);
                mma8(sacc[ntp*2+1], qf[kk][0], qf[kk][1], qf[kk][2], qf[kk][3], bb.z, bb.w);
            }
        }

#pragma unroll
        for (int nt = 0; nt < 8; nt++) {
            float ex = __expf(sacc[nt].x);
            float ey = __expf(sacc[nt].y);
            float ez = __expf(sacc[nt].z);
            float ew = __expf(sacc[nt].w);
            rs0 += ex + ey;
            rs1 += ez + ew;
            uint2 u01; u01.x = f2tf(ex); u01.y = f2tf(ey);
            uint2 u23; u23.x = f2tf(ez); u23.y = f2tf(ew);
            *(uint2*)&S.P1[R0 + ly][nt * 8 + lx * 2] = u01;
            *(uint2*)&S.P1[R0 + ly + 8][nt * 8 + lx * 2] = u23;
        }

        asm volatile("cp.async.wait_group 1;\n" ::: "memory");
        __syncwarp();

#pragma unroll
        for (int kk = 0; kk < 8; kk++) {
            int K0 = kk * 8;
            uint4 P = ldm4(p1base + ((unsigned)K0 << 2));
            uint4 C = ldm4(p2base + ((unsigned)K0 << 2));
#pragma unroll
            for (int nt = 0; nt < 4; nt++) {
                unsigned b0 = S.Vs[cur][K0 + lx][nt * 8 + ly];
                unsigned b1 = S.Vs[cur][K0 + lx + 4][nt * 8 + ly];
                mma8(opat[nt], P.x, P.y, P.z, P.w, b0, b1);
                mma8(opos[nt], C.x, C.y, C.z, C.w, b0, b1);
            }
        }
        __syncwarp();

#pragma unroll
        for (int l = 0; l < 8; l++) {
            int idx = lane + l * 32;
            int rr = idx >> 4, cq = (idx & 15) << 2;
            cpa16(&S.P2[R0 + rr][cq], &POSg[(size_t)(q0 + R0 + rr) * N_ + m1 + cq],
                  (q0 + R0 + rr < N_) && (m1 + cq < N_));
        }
        cpa_commit();
        asm volatile("cp.async.wait_group 1;\n" ::: "memory");
        __syncthreads();
    }

    // ---- peeled tail: it=12, m0=768, only 16 valid cols
    {
        unsigned ksc = ksb0;   // cur = 0
        float4 sacc[2];
        sacc[0] = make_float4(0.f,0.f,0.f,0.f);
        sacc[1] = sacc[0];
#pragma unroll
        for (int kk = 0; kk < 4; kk++) {
            int K0 = kk * 8;
            unsigned addr = ksc + (((brow) * QSTR + bcol + K0) << 2);
            uint4 bb = ldm4(addr);
            mma8(sacc[0], qf[kk][0], qf[kk][1], qf[kk][2], qf[kk][3], bb.x, bb.y);
            mma8(sacc[1], qf[kk][0], qf[kk][1], qf[kk][2], qf[kk][3], bb.z, bb.w);
        }
#pragma unroll
        for (int nt = 0; nt < 2; nt++) {
            float ex = __expf(sacc[nt].x);
            float ey = __expf(sacc[nt].y);
            float ez = __expf(sacc[nt].z);
            float ew = __expf(sacc[nt].w);
            rs0 += ex + ey;
            rs1 += ez + ew;
            uint2 u01; u01.x = f2tf(ex); u01.y = f2tf(ey);
            uint2 u23; u23.x = f2tf(ez); u23.y = f2tf(ew);
            *(uint2*)&S.P1[R0 + ly][nt * 8 + lx * 2] = u01;
            *(uint2*)&S.P1[R0 + ly + 8][nt * 8 + lx * 2] = u23;
        }
        asm volatile("cp.async.wait_group 0;\n" ::: "memory");
        __syncwarp();
#pragma unroll
        for (int kk = 0; kk < 2; kk++) {
            int K0 = kk * 8;
            uint4 P = ldm4(p1base + ((unsigned)K0 << 2));
            uint4 C = ldm4(p2base + ((unsigned)K0 << 2));
#pragma unroll
            for (int nt = 0; nt < 4; nt++) {
                unsigned b0 = S.Vs[0][K0 + lx][nt * 8 + ly];
                unsigned b1 = S.Vs[0][K0 + lx + 4][nt * 8 + ly];
                mma8(opat[nt], P.x, P.y, P.z, P.w, b0, b1);
                mma8(opos[nt], C.x, C.y, C.z, C.w, b0, b1);
            }
        }
    }

    rs0 += __shfl_xor_sync(0xffffffffu, rs0, 1);
    rs0 += __shfl_xor_sync(0xffffffffu, rs0, 2);
    rs1 += __shfl_xor_sync(0xffffffffu, rs1, 1);
    rs1 += __shfl_xor_sync(0xffffffffu, rs1, 2);
    float inv0 = (1.f - gate) / rs0;
    float inv1 = (1.f - gate) / rs1;

    // epilogue: write tf32 bits for gemm_out's raw fill
    int n0r = q0 + R0 + ly;
    int n1r = n0r + 8;
#pragma unroll
    for (int nt = 0; nt < 4; nt++) {
        int d = nt * 8 + lx * 2;
        if (n0r < N_) {
            float2 o;
            o.x = __uint_as_float(f2tf(opat[nt].x * inv0 + gate * opos[nt].x));
            o.y = __uint_as_float(f2tf(opat[nt].y * inv0 + gate * opos[nt].y));
            *(float2*)&g_att[((size_t)b * N_ + n0r) * DIM_ + h * HD_ + d] = o;
        }
        if (n1r < N_) {
            float2 o;
            o.x = __uint_as_float(f2tf(opat[nt].z * inv1 + gate * opos[nt].z));
            o.y = __uint_as_float(f2tf(opat[nt].w * inv1 + gate * opos[nt].w));
            *(float2*)&g_att[((size_t)b * N_ + n1r) * DIM_ + h * HD_ + d] = o;
        }
    }
}

// ---------------------------------------------------------------------------
extern "C" void kernel_launch(void* const* d_in, const int* in_sizes, int n_in,
                              void* d_out, int out_size) {
    const float* x      = (const float*)d_in[0];
    const float* Wq     = (const float*)d_in[1];
    const float* Wk     = (const float*)d_in[2];
    const float* Wv     = (const float*)d_in[3];
    const float* W_pos  = (const float*)d_in[4];
    const float* b_pos  = (const float*)d_in[5];
    const float* W_out  = (const float*)d_in[6];
    const float* b_out  = (const float*)d_in[7];
    const float* gating = (const float*)d_in[8];
    float* out = (float*)d_out;

    cudaFuncSetAttribute(attn_kernel, cudaFuncAttributeMaxDynamicSharedMemorySize,
                         (int)sizeof(ASmem));

    cvt_kernel<<<1024, 256>>>(x, Wq, Wk, Wv, W_out);
    pos_kernel<<<H_ * N_, 256>>>(W_pos, b_pos);

    gemm_qkv<<<dim3(3 * DIM_ / 64, ROWS_ / 64), 128>>>();                // (18, 98)

    attn_kernel<<<dim3(13, B_ * H_), 128, sizeof(ASmem)>>>(gating);

    gemm_out<<<dim3(DIM_ / 64, ROWS_ / 64), 128>>>(b_out, out);          // (6, 98)
}